// round 14
// baseline (speedup 1.0000x reference)
#include <cuda_runtime.h>
#include <cuda_bf16.h>
#include <math.h>
#include <stdint.h>

#define BB 2
#define SS 2048
#define EE 1024
#define HH 16
#define DD 64
#define MM (BB * SS)
#define KP 512          // k-pairs per row (EE/2)

// ---------------- scratch (device globals; no allocations allowed) ----------
__device__ uint2 g_wsp[4][KP * EE];     // weights split: [kpair][n] {hi2,lo2}
__device__ uint2 g_asp[3][MM * KP];     // input activations split
__device__ uint2 g_qsp[MM * KP];        // projected Q, scaled+split
__device__ uint2 g_ksp[MM * KP];        // projected K, split
__device__ float g_vp [MM * EE];        // projected V, fp32
__device__ uint2 g_vsp[BB * (SS / 2) * EE];  // V split, pairs along keys
__device__ uint2 g_atsp[MM * KP];       // attention output, split

// ======================= helpers ============================================
__device__ __forceinline__ uint32_t smem_u32(const void* p) {
    uint32_t a;
    asm("{ .reg .u64 t; cvta.to.shared.u64 t, %1; cvt.u32.u64 %0, t; }"
        : "=r"(a) : "l"(p));
    return a;
}
__device__ __forceinline__ void cp16(uint32_t dst, const void* src) {
    asm volatile("cp.async.cg.shared.global [%0], [%1], 16;" :: "r"(dst), "l"(src));
}
#define CP_COMMIT() asm volatile("cp.async.commit_group;" ::: "memory")
#define CP_WAIT0()  asm volatile("cp.async.wait_group 0;" ::: "memory")
#define CP_WAIT1()  asm volatile("cp.async.wait_group 1;" ::: "memory")
#define CP_WAIT2()  asm volatile("cp.async.wait_group 2;" ::: "memory")

__device__ __forceinline__ uint32_t packbf(float x0, float x1) {
    uint32_t r;
    asm("cvt.rn.bf16x2.f32 %0, %1, %2;" : "=r"(r) : "f"(x1), "f"(x0));
    return r;
}
__device__ __forceinline__ void bf_split2(float x0, float x1,
                                          uint32_t& h2, uint32_t& l2) {
    h2 = packbf(x0, x1);
    float h0 = __uint_as_float(h2 << 16);
    float h1 = __uint_as_float(h2 & 0xffff0000u);
    l2 = packbf(x0 - h0, x1 - h1);
}
__device__ __forceinline__ float ex2(float x) {
    float r;
    asm("ex2.approx.f32 %0, %1;" : "=f"(r) : "f"(x));
    return r;
}
__device__ __forceinline__ void mma_bf16(float* d, const uint32_t* a, const uint32_t* b) {
    asm volatile(
        "mma.sync.aligned.m16n8k16.row.col.f32.bf16.bf16.f32 "
        "{%0,%1,%2,%3}, {%4,%5,%6,%7}, {%8,%9}, {%0,%1,%2,%3};"
        : "+f"(d[0]), "+f"(d[1]), "+f"(d[2]), "+f"(d[3])
        : "r"(a[0]), "r"(a[1]), "r"(a[2]), "r"(a[3]), "r"(b[0]), "r"(b[1]));
}

// ======================= pre-split kernels ==================================
__global__ __launch_bounds__(256)
void split_w(const float* __restrict__ W0, const float* __restrict__ W1,
             const float* __restrict__ W2, const float* __restrict__ W3)
{
    const int z = blockIdx.z;
    const float* W = (z == 0) ? W0 : (z == 1) ? W1 : (z == 2) ? W2 : W3;
    uint2* out = g_wsp[z];
    const int idx = blockIdx.x * 256 + threadIdx.x;
    const int kp = idx >> 8;
    const int n = (idx & 255) * 4;
    float4 r0 = *(const float4*)&W[(size_t)(2 * kp) * EE + n];
    float4 r1 = *(const float4*)&W[(size_t)(2 * kp + 1) * EE + n];
    uint32_t hh, ll;
    bf_split2(r0.x, r1.x, hh, ll); out[(size_t)kp * EE + n + 0] = make_uint2(hh, ll);
    bf_split2(r0.y, r1.y, hh, ll); out[(size_t)kp * EE + n + 1] = make_uint2(hh, ll);
    bf_split2(r0.z, r1.z, hh, ll); out[(size_t)kp * EE + n + 2] = make_uint2(hh, ll);
    bf_split2(r0.w, r1.w, hh, ll); out[(size_t)kp * EE + n + 3] = make_uint2(hh, ll);
}

__global__ __launch_bounds__(256)
void split_act(const float* __restrict__ q, const float* __restrict__ k,
               const float* __restrict__ v)
{
    const int z = blockIdx.z;
    const float* src = (z == 0) ? q : (z == 1) ? k : v;
    uint2* out = g_asp[z];
    const int idx = blockIdx.x * 256 + threadIdx.x;
    const int row = idx >> 8;
    const int c = (idx & 255) * 4;
    float4 x = *(const float4*)&src[(size_t)row * EE + c];
    uint32_t hh, ll;
    bf_split2(x.x, x.y, hh, ll); out[(size_t)row * KP + c / 2]     = make_uint2(hh, ll);
    bf_split2(x.z, x.w, hh, ll); out[(size_t)row * KP + c / 2 + 1] = make_uint2(hh, ll);
}

// V: split with pairs along KEYS (adjacent seq rows), per column.
__global__ __launch_bounds__(256)
void split_v()
{
    const int idx = blockIdx.x * 256 + threadIdx.x;   // 2048*256
    const int b = idx >> 18;
    const int r = idx & 262143;
    const int kp = r >> 8;
    const int c4 = (r & 255) * 4;
    const size_t g0 = ((size_t)(b * SS + 2 * kp)) * EE + c4;
    float4 va = *(const float4*)&g_vp[g0];
    float4 vb = *(const float4*)&g_vp[g0 + EE];
    uint2* out = g_vsp + (size_t)(b * (SS / 2) + kp) * EE + c4;
    uint32_t hh, ll;
    bf_split2(va.x, vb.x, hh, ll); out[0] = make_uint2(hh, ll);
    bf_split2(va.y, vb.y, hh, ll); out[1] = make_uint2(hh, ll);
    bf_split2(va.z, vb.z, hh, ll); out[2] = make_uint2(hh, ll);
    bf_split2(va.w, vb.w, hh, ll); out[3] = make_uint2(hh, ll);
}

// ======================= GEMM (unchanged from R12) ==========================
#define GA_STR 20
#define GB_STR 132
#define ST_A_U2 (128 * GA_STR)
#define ST_B_U2 (16 * GB_STR)
#define ST_U2 (ST_A_U2 + ST_B_U2)
#define GEMM4_B (4 * ST_U2 * 8)

#define QSCALE 0.18033688011112042591f  // 0.125 * log2(e)

__device__ __forceinline__ void gemm_body(const uint2* __restrict__ Asp,
                                          const uint2* __restrict__ Wsp,
                                          const float* __restrict__ bias,
                                          float* __restrict__ Cf,
                                          uint2* __restrict__ Cp,
                                          int mode)
{
    extern __shared__ uint2 su[];
    const uint32_t sb0 = smem_u32(su);

    const int tid = threadIdx.x;
    const int lane = tid & 31;
    const int wid = tid >> 5;
    const int warpM = wid >> 2;
    const int warpN = wid & 3;
    const int bm = blockIdx.y * 128;
    const int bn = blockIdx.x * 128;
    const int lg = lane >> 2;
    const int lt = lane & 3;

    float acc[4][4][4];
#pragma unroll
    for (int mi = 0; mi < 4; mi++)
#pragma unroll
        for (int ni = 0; ni < 4; ni++)
#pragma unroll
            for (int r = 0; r < 4; r++) acc[mi][ni][r] = 0.0f;

    auto load = [&](int it) {
        const int st = it & 3;
        const uint32_t sa = sb0 + (uint32_t)(st * ST_U2) * 8;
        const uint32_t sbp = sa + ST_A_U2 * 8;
#pragma unroll
        for (int i = 0; i < 4; i++) {
            int cid = tid + i * 256;
            int row = cid >> 3, c2 = (cid & 7) * 2;
            cp16(sa + (uint32_t)(row * GA_STR + c2) * 8,
                 Asp + (size_t)(bm + row) * KP + it * 16 + c2);
        }
#pragma unroll
        for (int i = 0; i < 4; i++) {
            int cid = tid + i * 256;
            int kp = cid >> 6, c = (cid & 63) * 2;
            cp16(sbp + (uint32_t)(kp * GB_STR + c) * 8,
                 Wsp + (size_t)(it * 16 + kp) * EE + bn + c);
        }
    };

    load(0); CP_COMMIT();
    load(1); CP_COMMIT();
    load(2); CP_COMMIT();

    for (int it = 0; it < 32; it++) {
        if (it < 30) { CP_WAIT2(); } else if (it == 30) { CP_WAIT1(); } else { CP_WAIT0(); }
        __syncthreads();
        if (it + 3 < 32) { load(it + 3); CP_COMMIT(); }

        const uint2* Ah = su + (it & 3) * ST_U2;
        const uint2* Bh = Ah + ST_A_U2;

#pragma unroll
        for (int ks = 0; ks < 2; ks++) {
            uint32_t ah[4][4], al[4][4];
#pragma unroll
            for (int mi = 0; mi < 4; mi++) {
                int r = warpM * 64 + mi * 16 + lg;
                uint2 a0 = Ah[r * GA_STR + ks * 8 + lt];
                uint2 a1 = Ah[(r + 8) * GA_STR + ks * 8 + lt];
                uint2 a2 = Ah[r * GA_STR + ks * 8 + lt + 4];
                uint2 a3 = Ah[(r + 8) * GA_STR + ks * 8 + lt + 4];
                ah[mi][0] = a0.x; ah[mi][1] = a1.x; ah[mi][2] = a2.x; ah[mi][3] = a3.x;
                al[mi][0] = a0.y; al[mi][1] = a1.y; al[mi][2] = a2.y; al[mi][3] = a3.y;
            }
            uint32_t bh[4][2], bl[4][2];
#pragma unroll
            for (int ni = 0; ni < 4; ni++) {
                int col = warpN * 32 + ni * 8 + lg;
                uint2 b0 = Bh[(ks * 8 + lt) * GB_STR + col];
                uint2 b1 = Bh[(ks * 8 + lt + 4) * GB_STR + col];
                bh[ni][0] = b0.x; bh[ni][1] = b1.x;
                bl[ni][0] = b0.y; bl[ni][1] = b1.y;
            }
#pragma unroll
            for (int mi = 0; mi < 4; mi++)
#pragma unroll
                for (int ni = 0; ni < 4; ni++) {
                    mma_bf16(acc[mi][ni], ah[mi], bh[ni]);
                    mma_bf16(acc[mi][ni], al[mi], bh[ni]);
                    mma_bf16(acc[mi][ni], ah[mi], bl[ni]);
                }
        }
    }

    if (mode <= 1) {
        const float s = (mode == 0) ? QSCALE : 1.0f;
#pragma unroll
        for (int mi = 0; mi < 4; mi++) {
            const int row0 = bm + warpM * 64 + mi * 16 + lg;
#pragma unroll
            for (int ni = 0; ni < 4; ni++) {
                const int col = bn + warpN * 32 + ni * 8 + lt * 2;
                const float b0 = bias[col], b1 = bias[col + 1];
                uint32_t hh, ll;
                bf_split2((acc[mi][ni][0] + b0) * s, (acc[mi][ni][1] + b1) * s, hh, ll);
                Cp[(size_t)row0 * KP + col / 2] = make_uint2(hh, ll);
                bf_split2((acc[mi][ni][2] + b0) * s, (acc[mi][ni][3] + b1) * s, hh, ll);
                Cp[(size_t)(row0 + 8) * KP + col / 2] = make_uint2(hh, ll);
            }
        }
    } else {
#pragma unroll
        for (int mi = 0; mi < 4; mi++) {
            const int row0 = bm + warpM * 64 + mi * 16 + lg;
#pragma unroll
            for (int ni = 0; ni < 4; ni++) {
                const int col = bn + warpN * 32 + ni * 8 + lt * 2;
                const float b0 = bias[col], b1 = bias[col + 1];
                float2 v0 = make_float2(acc[mi][ni][0] + b0, acc[mi][ni][1] + b1);
                float2 v1 = make_float2(acc[mi][ni][2] + b0, acc[mi][ni][3] + b1);
                *(float2*)&Cf[(size_t)row0 * EE + col] = v0;
                *(float2*)&Cf[(size_t)(row0 + 8) * EE + col] = v1;
            }
        }
    }
}

__global__ __launch_bounds__(256, 1)
void gemm_qkv(const float* __restrict__ bq, const float* __restrict__ bk,
              const float* __restrict__ bv)
{
    const int z = blockIdx.z;
    const float* bias = (z == 0) ? bq : (z == 1) ? bk : bv;
    if (z == 0)      gemm_body(g_asp[0], g_wsp[0], bias, nullptr, g_qsp, 0);
    else if (z == 1) gemm_body(g_asp[1], g_wsp[1], bias, nullptr, g_ksp, 1);
    else             gemm_body(g_asp[2], g_wsp[2], bias, g_vp, nullptr, 2);
}

__global__ __launch_bounds__(256, 1)
void gemm_out(const float* __restrict__ bo, float* __restrict__ out)
{
    gemm_body(g_atsp, g_wsp[3], bo, out, nullptr, 3);
}

// ========== Flash attention: FQ=128, 256 thr, double-buffered K/V ===========
// 8 warps; warp w owns q-rows [w*16, w*16+16) x all 64 key cols. All operands
// pre-split (K from g_ksp, V from g_vsp via cp.async). Tile kt+1's loads are
// issued right after the top barrier so they overlap tile kt's compute.
#define FQ 128
#define PK_STR 36
#define FV_STR 68
#define KTILE_U2 (64 * PK_STR)              // 2304
#define VTILE_U2 (32 * FV_STR)              // 2176
#define BUF_U2 (KTILE_U2 + VTILE_U2)        // 4480
#define OFF_P_U2 0
#define OFF_B0_U2 (FQ * PK_STR)             // 4608
#define FLASH8_U2 (OFF_B0_U2 + 2 * BUF_U2)  // 13568
#define FLASH8_B (FLASH8_U2 * 8)            // 108544 bytes

__global__ __launch_bounds__(256, 1)
void flash_mma_kernel()
{
    extern __shared__ uint2 su[];
    uint2* Ph = su;

    const int tid = threadIdx.x;
    const int lane = tid & 31;
    const int w = tid >> 5;
    const int lg = lane >> 2;
    const int lt = lane & 3;
    const int qt = (gridDim.x - 1) - blockIdx.x;   // big tiles first
    const int hd = blockIdx.y;
    const int b = blockIdx.z;
    const int qbase = qt * FQ;
    const int hp = hd * 32;

    // Q fragments: direct LDG of pre-split, pre-scaled pairs
    const int r0 = w * 16 + lg;
    uint32_t qh[4][4], ql[4][4];
    {
        const size_t base0 = (size_t)(b * SS + qbase + r0) * KP + hp;
        const size_t base1 = base0 + 8 * KP;
#pragma unroll
        for (int ks = 0; ks < 4; ks++) {
            uint2 a0 = g_qsp[base0 + ks * 8 + lt];
            uint2 a1 = g_qsp[base1 + ks * 8 + lt];
            uint2 a2 = g_qsp[base0 + ks * 8 + lt + 4];
            uint2 a3 = g_qsp[base1 + ks * 8 + lt + 4];
            qh[ks][0] = a0.x; qh[ks][1] = a1.x; qh[ks][2] = a2.x; qh[ks][3] = a3.x;
            ql[ks][0] = a0.y; ql[ks][1] = a1.y; ql[ks][2] = a2.y; ql[ks][3] = a3.y;
        }
    }

    // tile loader: K (64 rows x 32 pairs) + V (32 key-pairs x 64 cols)
    auto load_tile = [&](int kt) {
        uint2* Kb = su + OFF_B0_U2 + (kt & 1) * BUF_U2;
        uint2* Vb = Kb + KTILE_U2;
        const int kbase = kt * 64;
#pragma unroll
        for (int i = 0; i < 4; i++) {
            int cid = tid + i * 256;
            int row = cid >> 4, c2 = (cid & 15) * 2;
            cp16(smem_u32(Kb + row * PK_STR + c2),
                 g_ksp + (size_t)(b * SS + kbase + row) * KP + hp + c2);
        }
#pragma unroll
        for (int i = 0; i < 4; i++) {
            int cid = tid + i * 256;
            int kp = cid >> 5, c2 = (cid & 31) * 2;
            cp16(smem_u32(Vb + kp * FV_STR + c2),
                 g_vsp + (size_t)(b * (SS / 2) + kbase / 2 + kp) * EE + hd * DD + c2);
        }
    };

    float oacc[8][4];
#pragma unroll
    for (int ni = 0; ni < 8; ni++)
#pragma unroll
        for (int r = 0; r < 4; r++) oacc[ni][r] = 0.0f;
    float m0 = -1e30f, m1 = -1e30f, l0 = 0.0f, l1 = 0.0f;

    const int nkt = (qbase + FQ) / 64;

    load_tile(0); CP_COMMIT();

    for (int kt = 0; kt < nkt; kt++) {
        const int kbase = kt * 64;
        CP_WAIT0();          // tile kt landed (one group in flight)
        __syncthreads();     // + all warps done reading buf[(kt+1)&1] (from kt-1)
        if (kt + 1 < nkt) { load_tile(kt + 1); CP_COMMIT(); }   // overlaps compute

        const uint2* Kh = su + OFF_B0_U2 + (kt & 1) * BUF_U2;
        const uint2* Vh = Kh + KTILE_U2;

        // ---- S = Q @ K^T
        float sacc[8][4];
#pragma unroll
        for (int ni = 0; ni < 8; ni++)
#pragma unroll
            for (int r = 0; r < 4; r++) sacc[ni][r] = 0.0f;

#pragma unroll
        for (int ks = 0; ks < 4; ks++) {
#pragma unroll
            for (int ni = 0; ni < 8; ni++) {
                const int krow = ni * 8 + lg;
                uint2 k0 = Kh[krow * PK_STR + ks * 8 + lt];
                uint2 k1 = Kh[krow * PK_STR + ks * 8 + lt + 4];
                uint32_t bh[2] = {k0.x, k1.x};
                uint32_t bl[2] = {k0.y, k1.y};
                mma_bf16(sacc[ni], qh[ks], bh);
                mma_bf16(sacc[ni], ql[ks], bh);
                mma_bf16(sacc[ni], qh[ks], bl);
            }
        }

        // ---- causal mask (near-diagonal tiles only)
        if (kt >= 2 * qt) {
            const int grow0 = qbase + r0;
#pragma unroll
            for (int ni = 0; ni < 8; ni++) {
                const int c0 = kbase + ni * 8 + lt * 2;
                if (c0 > grow0)         sacc[ni][0] = -1e30f;
                if (c0 + 1 > grow0)     sacc[ni][1] = -1e30f;
                if (c0 > grow0 + 8)     sacc[ni][2] = -1e30f;
                if (c0 + 1 > grow0 + 8) sacc[ni][3] = -1e30f;
            }
        }

        // ---- online softmax (base-2)
        float rmax0 = -1e30f, rmax1 = -1e30f;
#pragma unroll
        for (int ni = 0; ni < 8; ni++) {
            rmax0 = fmaxf(rmax0, fmaxf(sacc[ni][0], sacc[ni][1]));
            rmax1 = fmaxf(rmax1, fmaxf(sacc[ni][2], sacc[ni][3]));
        }
        rmax0 = fmaxf(rmax0, __shfl_xor_sync(0xffffffffu, rmax0, 1));
        rmax0 = fmaxf(rmax0, __shfl_xor_sync(0xffffffffu, rmax0, 2));
        rmax1 = fmaxf(rmax1, __shfl_xor_sync(0xffffffffu, rmax1, 1));
        rmax1 = fmaxf(rmax1, __shfl_xor_sync(0xffffffffu, rmax1, 2));

        const float newm0 = fmaxf(m0, rmax0);
        const float newm1 = fmaxf(m1, rmax1);
        const float alpha0 = ex2(m0 - newm0);
        const float alpha1 = ex2(m1 - newm1);
        m0 = newm0; m1 = newm1;

        float rsum0 = 0.0f, rsum1 = 0.0f;
#pragma unroll
        for (int ni = 0; ni < 8; ni++) {
            sacc[ni][0] = ex2(sacc[ni][0] - m0);
            sacc[ni][1] = ex2(sacc[ni][1] - m0);
            sacc[ni][2] = ex2(sacc[ni][2] - m1);
            sacc[ni][3] = ex2(sacc[ni][3] - m1);
            rsum0 += sacc[ni][0] + sacc[ni][1];
            rsum1 += sacc[ni][2] + sacc[ni][3];
        }
        rsum0 += __shfl_xor_sync(0xffffffffu, rsum0, 1);
        rsum0 += __shfl_xor_sync(0xffffffffu, rsum0, 2);
        rsum1 += __shfl_xor_sync(0xffffffffu, rsum1, 1);
        rsum1 += __shfl_xor_sync(0xffffffffu, rsum1, 2);
        l0 = l0 * alpha0 + rsum0;
        l1 = l1 * alpha1 + rsum1;

        // rescale O; split P once; store packed {hi2,lo2}
#pragma unroll
        for (int ni = 0; ni < 8; ni++) {
            oacc[ni][0] *= alpha0;
            oacc[ni][1] *= alpha0;
            oacc[ni][2] *= alpha1;
            oacc[ni][3] *= alpha1;
            uint32_t hh, ll;
            bf_split2(sacc[ni][0], sacc[ni][1], hh, ll);
            Ph[r0 * PK_STR + ni * 4 + lt] = make_uint2(hh, ll);
            bf_split2(sacc[ni][2], sacc[ni][3], hh, ll);
            Ph[(r0 + 8) * PK_STR + ni * 4 + lt] = make_uint2(hh, ll);
        }
        __syncwarp();   // warp reads only its own P rows

        // ---- O += P @ V
#pragma unroll
        for (int ks = 0; ks < 4; ks++) {
            uint2 p0 = Ph[r0 * PK_STR + ks * 8 + lt];
            uint2 p1 = Ph[(r0 + 8) * PK_STR + ks * 8 + lt];
            uint2 p2 = Ph[r0 * PK_STR + ks * 8 + lt + 4];
            uint2 p3 = Ph[(r0 + 8) * PK_STR + ks * 8 + lt + 4];
            uint32_t ph[4] = {p0.x, p1.x, p2.x, p3.x};
            uint32_t pl[4] = {p0.y, p1.y, p2.y, p3.y};
#pragma unroll
            for (int ni = 0; ni < 8; ni++) {
                const int col = ni * 8 + lg;
                uint2 v0 = Vh[(ks * 8 + lt) * FV_STR + col];
                uint2 v1 = Vh[(ks * 8 + lt + 4) * FV_STR + col];
                uint32_t bh[2] = {v0.x, v1.x};
                uint32_t bl[2] = {v0.y, v1.y};
                mma_bf16(oacc[ni], ph, bh);
                mma_bf16(oacc[ni], pl, bh);
                mma_bf16(oacc[ni], ph, bl);
            }
        }
    }

    // ---- epilogue: write attention output as split pairs for gemm_out
    const float inv0 = 1.0f / l0;
    const float inv1 = 1.0f / l1;
    const int grow = qbase + r0;
#pragma unroll
    for (int ni = 0; ni < 8; ni++) {
        uint32_t hh, ll;
        bf_split2(oacc[ni][0] * inv0, oacc[ni][1] * inv0, hh, ll);
        g_atsp[(size_t)(b * SS + grow) * KP + hp + ni * 4 + lt] = make_uint2(hh, ll);
        bf_split2(oacc[ni][2] * inv1, oacc[ni][3] * inv1, hh, ll);
        g_atsp[(size_t)(b * SS + grow + 8) * KP + hp + ni * 4 + lt] = make_uint2(hh, ll);
    }
}

// ---------------- launch ----------------------------------------------------
extern "C" void kernel_launch(void* const* d_in, const int* in_sizes, int n_in,
                              void* d_out, int out_size)
{
    const float* q  = (const float*)d_in[0];
    const float* k  = (const float*)d_in[1];
    const float* v  = (const float*)d_in[2];
    const float* Wq = (const float*)d_in[3];
    const float* bq = (const float*)d_in[4];
    const float* Wk = (const float*)d_in[5];
    const float* bk = (const float*)d_in[6];
    const float* Wv = (const float*)d_in[7];
    const float* bv = (const float*)d_in[8];
    const float* Wo = (const float*)d_in[9];
    const float* bo = (const float*)d_in[10];
    float* out = (float*)d_out;

    cudaFuncSetAttribute(gemm_qkv,
                         cudaFuncAttributeMaxDynamicSharedMemorySize, GEMM4_B);
    cudaFuncSetAttribute(gemm_out,
                         cudaFuncAttributeMaxDynamicSharedMemorySize, GEMM4_B);
    cudaFuncSetAttribute(flash_mma_kernel,
                         cudaFuncAttributeMaxDynamicSharedMemorySize, FLASH8_B);

    dim3 wgrid(512, 1, 4);
    split_w<<<wgrid, 256>>>(Wq, Wk, Wv, Wo);
    dim3 agrid(4096, 1, 3);
    split_act<<<agrid, 256>>>(q, k, v);

    dim3 qkv_grid(EE / 128, MM / 128, 3);
    gemm_qkv<<<qkv_grid, 256, GEMM4_B>>>(bq, bk, bv);

    split_v<<<2048, 256>>>();

    dim3 fa_grid(SS / FQ, HH, BB);          // (16, 16, 2)
    flash_mma_kernel<<<fa_grid, 256, FLASH8_B>>>();

    dim3 ogrid(EE / 128, MM / 128);
    gemm_out<<<ogrid, 256, GEMM4_B>>>(bo, out);
}

// round 15
// speedup vs baseline: 1.5310x; 1.5310x over previous
#include <cuda_runtime.h>
#include <cuda_bf16.h>
#include <math.h>
#include <stdint.h>

#define BB 2
#define SS 2048
#define EE 1024
#define HH 16
#define DD 64
#define MM (BB * SS)
#define KP 512          // k-pairs per row (EE/2)

// ---------------- scratch (device globals; no allocations allowed) ----------
__device__ uint2 g_wsp[4][KP * EE];     // weights split: [kpair][n] {hi2,lo2}
__device__ uint2 g_asp[3][MM * KP];     // input activations split
__device__ uint2 g_qsp[MM * KP];        // projected Q, scaled+split
__device__ uint2 g_ksp[MM * KP];        // projected K, split
__device__ float g_vp [MM * EE];        // projected V, fp32
__device__ uint2 g_atsp[MM * KP];       // attention output, split

// ======================= helpers ============================================
__device__ __forceinline__ uint32_t smem_u32(const void* p) {
    uint32_t a;
    asm("{ .reg .u64 t; cvta.to.shared.u64 t, %1; cvt.u32.u64 %0, t; }"
        : "=r"(a) : "l"(p));
    return a;
}
__device__ __forceinline__ void cp16(uint32_t dst, const void* src) {
    asm volatile("cp.async.cg.shared.global [%0], [%1], 16;" :: "r"(dst), "l"(src));
}
#define CP_COMMIT() asm volatile("cp.async.commit_group;" ::: "memory")
#define CP_WAIT0()  asm volatile("cp.async.wait_group 0;" ::: "memory")
#define CP_WAIT1()  asm volatile("cp.async.wait_group 1;" ::: "memory")

__device__ __forceinline__ uint32_t packbf(float x0, float x1) {
    uint32_t r;
    asm("cvt.rn.bf16x2.f32 %0, %1, %2;" : "=r"(r) : "f"(x1), "f"(x0));
    return r;
}
__device__ __forceinline__ void bf_split2(float x0, float x1,
                                          uint32_t& h2, uint32_t& l2) {
    h2 = packbf(x0, x1);
    float h0 = __uint_as_float(h2 << 16);
    float h1 = __uint_as_float(h2 & 0xffff0000u);
    l2 = packbf(x0 - h0, x1 - h1);
}
__device__ __forceinline__ float ex2(float x) {
    float r;
    asm("ex2.approx.f32 %0, %1;" : "=f"(r) : "f"(x));
    return r;
}
__device__ __forceinline__ void mma_bf16(float* d, const uint32_t* a, const uint32_t* b) {
    asm volatile(
        "mma.sync.aligned.m16n8k16.row.col.f32.bf16.bf16.f32 "
        "{%0,%1,%2,%3}, {%4,%5,%6,%7}, {%8,%9}, {%0,%1,%2,%3};"
        : "+f"(d[0]), "+f"(d[1]), "+f"(d[2]), "+f"(d[3])
        : "r"(a[0]), "r"(a[1]), "r"(a[2]), "r"(a[3]), "r"(b[0]), "r"(b[1]));
}

// ======================= pre-split kernels (exact R12) ======================
__global__ __launch_bounds__(256)
void split_w(const float* __restrict__ W0, const float* __restrict__ W1,
             const float* __restrict__ W2, const float* __restrict__ W3)
{
    const int z = blockIdx.z;
    const float* W = (z == 0) ? W0 : (z == 1) ? W1 : (z == 2) ? W2 : W3;
    uint2* out = g_wsp[z];
    const int idx = blockIdx.x * 256 + threadIdx.x;
    const int kp = idx >> 8;
    const int n = (idx & 255) * 4;
    float4 r0 = *(const float4*)&W[(size_t)(2 * kp) * EE + n];
    float4 r1 = *(const float4*)&W[(size_t)(2 * kp + 1) * EE + n];
    uint32_t hh, ll;
    bf_split2(r0.x, r1.x, hh, ll); out[(size_t)kp * EE + n + 0] = make_uint2(hh, ll);
    bf_split2(r0.y, r1.y, hh, ll); out[(size_t)kp * EE + n + 1] = make_uint2(hh, ll);
    bf_split2(r0.z, r1.z, hh, ll); out[(size_t)kp * EE + n + 2] = make_uint2(hh, ll);
    bf_split2(r0.w, r1.w, hh, ll); out[(size_t)kp * EE + n + 3] = make_uint2(hh, ll);
}

__global__ __launch_bounds__(256)
void split_act(const float* __restrict__ q, const float* __restrict__ k,
               const float* __restrict__ v)
{
    const int z = blockIdx.z;
    const float* src = (z == 0) ? q : (z == 1) ? k : v;
    uint2* out = g_asp[z];
    const int idx = blockIdx.x * 256 + threadIdx.x;
    const int row = idx >> 8;
    const int c = (idx & 255) * 4;
    float4 x = *(const float4*)&src[(size_t)row * EE + c];
    uint32_t hh, ll;
    bf_split2(x.x, x.y, hh, ll); out[(size_t)row * KP + c / 2]     = make_uint2(hh, ll);
    bf_split2(x.z, x.w, hh, ll); out[(size_t)row * KP + c / 2 + 1] = make_uint2(hh, ll);
}

// ======================= GEMM: 256x128 CTA tile, warp 64x64 =================
// C = A @ W + bias. K-chunk 32, 8 warps as 4M x 2N, m16n8k16, 3-term split,
// 3-stage cp.async pipeline (proven 2-ahead structure).
#define GA_STR 20            // A smem stride (uint2)
#define GB_STR 132           // B smem stride (uint2)
#define ST_A_U2 (256 * GA_STR)          // 5120
#define ST_B_U2 (16 * GB_STR)           // 2112
#define ST_U2 (ST_A_U2 + ST_B_U2)       // 7232
#define GEMM5_B (3 * ST_U2 * 8)         // 173568 bytes

#define QSCALE 0.18033688011112042591f  // 0.125 * log2(e)

__device__ __forceinline__ void gemm_body(const uint2* __restrict__ Asp,
                                          const uint2* __restrict__ Wsp,
                                          const float* __restrict__ bias,
                                          float* __restrict__ Cf,
                                          uint2* __restrict__ Cp,
                                          int mode)   // 0:Q split+scale 1:K split 2/3: fp32
{
    extern __shared__ uint2 su[];
    const uint32_t sb0 = smem_u32(su);

    const int tid = threadIdx.x;
    const int lane = tid & 31;
    const int wid = tid >> 5;
    const int warpM = wid >> 1;          // 0..3 -> 64 rows each
    const int warpN = wid & 1;           // 0..1 -> 64 cols each
    const int bm = blockIdx.y * 256;
    const int bn = blockIdx.x * 128;
    const int lg = lane >> 2;
    const int lt = lane & 3;

    float acc[4][8][4];
#pragma unroll
    for (int mi = 0; mi < 4; mi++)
#pragma unroll
        for (int ni = 0; ni < 8; ni++)
#pragma unroll
            for (int r = 0; r < 4; r++) acc[mi][ni][r] = 0.0f;

    auto load = [&](int it) {
        const int st = it % 3;
        const uint32_t sa = sb0 + (uint32_t)(st * ST_U2) * 8;
        const uint32_t sbp = sa + ST_A_U2 * 8;
#pragma unroll
        for (int i = 0; i < 8; i++) {           // A: 256 rows x 16 u2
            int cid = tid + i * 256;
            int row = cid >> 3, c2 = (cid & 7) * 2;
            cp16(sa + (uint32_t)(row * GA_STR + c2) * 8,
                 Asp + (size_t)(bm + row) * KP + it * 16 + c2);
        }
#pragma unroll
        for (int i = 0; i < 4; i++) {           // B: 16 kp x 128 u2
            int cid = tid + i * 256;
            int kp = cid >> 6, c = (cid & 63) * 2;
            cp16(sbp + (uint32_t)(kp * GB_STR + c) * 8,
                 Wsp + (size_t)(it * 16 + kp) * EE + bn + c);
        }
    };

    load(0); CP_COMMIT();
    load(1); CP_COMMIT();

    for (int it = 0; it < 32; it++) {
        if (it == 31) { CP_WAIT0(); } else { CP_WAIT1(); }
        __syncthreads();
        if (it + 2 < 32) { load(it + 2); CP_COMMIT(); }

        const uint2* Ah = su + (it % 3) * ST_U2;
        const uint2* Bh = Ah + ST_A_U2;

#pragma unroll
        for (int ks = 0; ks < 2; ks++) {
            uint32_t ah[4][4], al[4][4];
#pragma unroll
            for (int mi = 0; mi < 4; mi++) {
                int r = warpM * 64 + mi * 16 + lg;
                uint2 a0 = Ah[r * GA_STR + ks * 8 + lt];
                uint2 a1 = Ah[(r + 8) * GA_STR + ks * 8 + lt];
                uint2 a2 = Ah[r * GA_STR + ks * 8 + lt + 4];
                uint2 a3 = Ah[(r + 8) * GA_STR + ks * 8 + lt + 4];
                ah[mi][0] = a0.x; ah[mi][1] = a1.x; ah[mi][2] = a2.x; ah[mi][3] = a3.x;
                al[mi][0] = a0.y; al[mi][1] = a1.y; al[mi][2] = a2.y; al[mi][3] = a3.y;
            }
#pragma unroll
            for (int ni = 0; ni < 8; ni++) {
                int col = warpN * 64 + ni * 8 + lg;
                uint2 b0 = Bh[(ks * 8 + lt) * GB_STR + col];
                uint2 b1 = Bh[(ks * 8 + lt + 4) * GB_STR + col];
                uint32_t bh[2] = {b0.x, b1.x};
                uint32_t bl[2] = {b0.y, b1.y};
#pragma unroll
                for (int mi = 0; mi < 4; mi++) {
                    mma_bf16(acc[mi][ni], ah[mi], bh);
                    mma_bf16(acc[mi][ni], al[mi], bh);
                    mma_bf16(acc[mi][ni], ah[mi], bl);
                }
            }
        }
    }

    if (mode <= 1) {
        const float s = (mode == 0) ? QSCALE : 1.0f;
#pragma unroll
        for (int mi = 0; mi < 4; mi++) {
            const int row0 = bm + warpM * 64 + mi * 16 + lg;
#pragma unroll
            for (int ni = 0; ni < 8; ni++) {
                const int col = bn + warpN * 64 + ni * 8 + lt * 2;
                const float b0 = bias[col], b1 = bias[col + 1];
                uint32_t hh, ll;
                bf_split2((acc[mi][ni][0] + b0) * s, (acc[mi][ni][1] + b1) * s, hh, ll);
                Cp[(size_t)row0 * KP + col / 2] = make_uint2(hh, ll);
                bf_split2((acc[mi][ni][2] + b0) * s, (acc[mi][ni][3] + b1) * s, hh, ll);
                Cp[(size_t)(row0 + 8) * KP + col / 2] = make_uint2(hh, ll);
            }
        }
    } else {
#pragma unroll
        for (int mi = 0; mi < 4; mi++) {
            const int row0 = bm + warpM * 64 + mi * 16 + lg;
#pragma unroll
            for (int ni = 0; ni < 8; ni++) {
                const int col = bn + warpN * 64 + ni * 8 + lt * 2;
                const float b0 = bias[col], b1 = bias[col + 1];
                float2 v0 = make_float2(acc[mi][ni][0] + b0, acc[mi][ni][1] + b1);
                float2 v1 = make_float2(acc[mi][ni][2] + b0, acc[mi][ni][3] + b1);
                *(float2*)&Cf[(size_t)row0 * EE + col] = v0;
                *(float2*)&Cf[(size_t)(row0 + 8) * EE + col] = v1;
            }
        }
    }
}

__global__ __launch_bounds__(256, 1)
void gemm_qkv(const float* __restrict__ bq, const float* __restrict__ bk,
              const float* __restrict__ bv)
{
    const int z = blockIdx.z;
    const float* bias = (z == 0) ? bq : (z == 1) ? bk : bv;
    if (z == 0)      gemm_body(g_asp[0], g_wsp[0], bias, nullptr, g_qsp, 0);
    else if (z == 1) gemm_body(g_asp[1], g_wsp[1], bias, nullptr, g_ksp, 1);
    else             gemm_body(g_asp[2], g_wsp[2], bias, g_vp, nullptr, 2);
}

__global__ __launch_bounds__(256, 1)
void gemm_out(const float* __restrict__ bo, float* __restrict__ out)
{
    gemm_body(g_atsp, g_wsp[3], bo, out, nullptr, 3);
}

// ================= Flash attention (EXACT R12 version) ======================
#define PK_STR 36
#define FV_STR 68
#define OFF_K_U2 (128 * PK_STR)             // 4608 (after Ph)
#define OFF_V_U2 (OFF_K_U2 + 64 * PK_STR)   // 6912
#define FLASH6_U2 (OFF_V_U2 + 32 * FV_STR)  // 9088
#define FLASH6_B (FLASH6_U2 * 8)            // 72704 bytes

__global__ __launch_bounds__(256, 1)
void flash_mma_kernel()
{
    extern __shared__ uint2 su[];
    uint2* Ph = su;
    uint2* Kh = su + OFF_K_U2;
    uint2* Vh = su + OFF_V_U2;

    const int tid = threadIdx.x;
    const int lane = tid & 31;
    const int w = tid >> 5;
    const int lg = lane >> 2;
    const int lt = lane & 3;
    const int qt = (gridDim.x - 1) - blockIdx.x;
    const int hd = blockIdx.y;
    const int b = blockIdx.z;
    const int qbase = qt * 128;
    const int hp = hd * 32;                  // head offset in pairs

    // Q fragments: direct LDG of pre-split, pre-scaled pairs
    const int r0 = w * 16 + lg;
    uint32_t qh[4][4], ql[4][4];
    {
        const size_t base0 = (size_t)(b * SS + qbase + r0) * KP + hp;
        const size_t base1 = base0 + 8 * KP;
#pragma unroll
        for (int ks = 0; ks < 4; ks++) {
            uint2 a0 = g_qsp[base0 + ks * 8 + lt];
            uint2 a1 = g_qsp[base1 + ks * 8 + lt];
            uint2 a2 = g_qsp[base0 + ks * 8 + lt + 4];
            uint2 a3 = g_qsp[base1 + ks * 8 + lt + 4];
            qh[ks][0] = a0.x; qh[ks][1] = a1.x; qh[ks][2] = a2.x; qh[ks][3] = a3.x;
            ql[ks][0] = a0.y; ql[ks][1] = a1.y; ql[ks][2] = a2.y; ql[ks][3] = a3.y;
        }
    }

    float oacc[8][4];
#pragma unroll
    for (int ni = 0; ni < 8; ni++)
#pragma unroll
        for (int r = 0; r < 4; r++) oacc[ni][r] = 0.0f;
    float m0 = -1e30f, m1 = -1e30f, l0 = 0.0f, l1 = 0.0f;

    const int nkt = (qbase + 128) / 64;

    for (int kt = 0; kt < nkt; kt++) {
        const int kbase = kt * 64;
        __syncthreads();
        // K tile: cp.async of pre-split pairs (zero CVT)
#pragma unroll
        for (int i = 0; i < 4; i++) {
            int cid = tid + i * 256;
            int row = cid >> 4, c2 = (cid & 15) * 2;
            cp16(smem_u32(Kh + row * PK_STR + c2),
                 g_ksp + (size_t)(b * SS + kbase + row) * KP + hp + c2);
        }
        CP_COMMIT();
        // V tile: fp32 -> split (pairs along key)
#pragma unroll
        for (int i = 0; i < 2; i++) {
            int s = tid + i * 256;
            int kp = s >> 4, c4 = (s & 15) * 4;
            const size_t g0 = ((size_t)(b * SS + kbase + 2 * kp)) * EE + hd * DD + c4;
            float4 va = *(const float4*)&g_vp[g0];
            float4 vb = *(const float4*)&g_vp[g0 + EE];
            uint32_t hh, ll;
            uint4 w0, w1;
            bf_split2(va.x, vb.x, hh, ll); w0.x = hh; w0.y = ll;
            bf_split2(va.y, vb.y, hh, ll); w0.z = hh; w0.w = ll;
            bf_split2(va.z, vb.z, hh, ll); w1.x = hh; w1.y = ll;
            bf_split2(va.w, vb.w, hh, ll); w1.z = hh; w1.w = ll;
            *(uint4*)&Vh[kp * FV_STR + c4] = w0;
            *(uint4*)&Vh[kp * FV_STR + c4 + 2] = w1;
        }
        CP_WAIT0();
        __syncthreads();

        // ---- S = Q @ K^T
        float sacc[8][4];
#pragma unroll
        for (int ni = 0; ni < 8; ni++)
#pragma unroll
            for (int r = 0; r < 4; r++) sacc[ni][r] = 0.0f;

#pragma unroll
        for (int ks = 0; ks < 4; ks++) {
#pragma unroll
            for (int ni = 0; ni < 8; ni++) {
                const int krow = ni * 8 + lg;
                uint2 k0 = Kh[krow * PK_STR + ks * 8 + lt];
                uint2 k1 = Kh[krow * PK_STR + ks * 8 + lt + 4];
                uint32_t bh[2] = {k0.x, k1.x};
                uint32_t bl[2] = {k0.y, k1.y};
                mma_bf16(sacc[ni], qh[ks], bh);
                mma_bf16(sacc[ni], ql[ks], bh);
                mma_bf16(sacc[ni], qh[ks], bl);
            }
        }

        if (kt >= 2 * qt) {
            const int grow0 = qbase + r0;
#pragma unroll
            for (int ni = 0; ni < 8; ni++) {
                const int c0 = kbase + ni * 8 + lt * 2;
                if (c0 > grow0)         sacc[ni][0] = -1e30f;
                if (c0 + 1 > grow0)     sacc[ni][1] = -1e30f;
                if (c0 > grow0 + 8)     sacc[ni][2] = -1e30f;
                if (c0 + 1 > grow0 + 8) sacc[ni][3] = -1e30f;
            }
        }

        float rmax0 = -1e30f, rmax1 = -1e30f;
#pragma unroll
        for (int ni = 0; ni < 8; ni++) {
            rmax0 = fmaxf(rmax0, fmaxf(sacc[ni][0], sacc[ni][1]));
            rmax1 = fmaxf(rmax1, fmaxf(sacc[ni][2], sacc[ni][3]));
        }
        rmax0 = fmaxf(rmax0, __shfl_xor_sync(0xffffffffu, rmax0, 1));
        rmax0 = fmaxf(rmax0, __shfl_xor_sync(0xffffffffu, rmax0, 2));
        rmax1 = fmaxf(rmax1, __shfl_xor_sync(0xffffffffu, rmax1, 1));
        rmax1 = fmaxf(rmax1, __shfl_xor_sync(0xffffffffu, rmax1, 2));

        const float newm0 = fmaxf(m0, rmax0);
        const float newm1 = fmaxf(m1, rmax1);
        const float alpha0 = ex2(m0 - newm0);
        const float alpha1 = ex2(m1 - newm1);
        m0 = newm0; m1 = newm1;

        float rsum0 = 0.0f, rsum1 = 0.0f;
#pragma unroll
        for (int ni = 0; ni < 8; ni++) {
            sacc[ni][0] = ex2(sacc[ni][0] - m0);
            sacc[ni][1] = ex2(sacc[ni][1] - m0);
            sacc[ni][2] = ex2(sacc[ni][2] - m1);
            sacc[ni][3] = ex2(sacc[ni][3] - m1);
            rsum0 += sacc[ni][0] + sacc[ni][1];
            rsum1 += sacc[ni][2] + sacc[ni][3];
        }
        rsum0 += __shfl_xor_sync(0xffffffffu, rsum0, 1);
        rsum0 += __shfl_xor_sync(0xffffffffu, rsum0, 2);
        rsum1 += __shfl_xor_sync(0xffffffffu, rsum1, 1);
        rsum1 += __shfl_xor_sync(0xffffffffu, rsum1, 2);
        l0 = l0 * alpha0 + rsum0;
        l1 = l1 * alpha1 + rsum1;

#pragma unroll
        for (int ni = 0; ni < 8; ni++) {
            oacc[ni][0] *= alpha0;
            oacc[ni][1] *= alpha0;
            oacc[ni][2] *= alpha1;
            oacc[ni][3] *= alpha1;
            uint32_t hh, ll;
            bf_split2(sacc[ni][0], sacc[ni][1], hh, ll);
            Ph[r0 * PK_STR + ni * 4 + lt] = make_uint2(hh, ll);
            bf_split2(sacc[ni][2], sacc[ni][3], hh, ll);
            Ph[(r0 + 8) * PK_STR + ni * 4 + lt] = make_uint2(hh, ll);
        }
        __syncwarp();

#pragma unroll
        for (int ks = 0; ks < 4; ks++) {
            uint2 p0 = Ph[r0 * PK_STR + ks * 8 + lt];
            uint2 p1 = Ph[(r0 + 8) * PK_STR + ks * 8 + lt];
            uint2 p2 = Ph[r0 * PK_STR + ks * 8 + lt + 4];
            uint2 p3 = Ph[(r0 + 8) * PK_STR + ks * 8 + lt + 4];
            uint32_t ph[4] = {p0.x, p1.x, p2.x, p3.x};
            uint32_t pl[4] = {p0.y, p1.y, p2.y, p3.y};
#pragma unroll
            for (int ni = 0; ni < 8; ni++) {
                const int col = ni * 8 + lg;
                uint2 v0 = Vh[(ks * 8 + lt) * FV_STR + col];
                uint2 v1 = Vh[(ks * 8 + lt + 4) * FV_STR + col];
                uint32_t bh[2] = {v0.x, v1.x};
                uint32_t bl[2] = {v0.y, v1.y};
                mma_bf16(oacc[ni], ph, bh);
                mma_bf16(oacc[ni], pl, bh);
                mma_bf16(oacc[ni], ph, bl);
            }
        }
    }

    const float inv0 = 1.0f / l0;
    const float inv1 = 1.0f / l1;
    const int grow = qbase + r0;
#pragma unroll
    for (int ni = 0; ni < 8; ni++) {
        uint32_t hh, ll;
        bf_split2(oacc[ni][0] * inv0, oacc[ni][1] * inv0, hh, ll);
        g_atsp[(size_t)(b * SS + grow) * KP + hp + ni * 4 + lt] = make_uint2(hh, ll);
        bf_split2(oacc[ni][2] * inv1, oacc[ni][3] * inv1, hh, ll);
        g_atsp[(size_t)(b * SS + grow + 8) * KP + hp + ni * 4 + lt] = make_uint2(hh, ll);
    }
}

// ---------------- launch ----------------------------------------------------
extern "C" void kernel_launch(void* const* d_in, const int* in_sizes, int n_in,
                              void* d_out, int out_size)
{
    const float* q  = (const float*)d_in[0];
    const float* k  = (const float*)d_in[1];
    const float* v  = (const float*)d_in[2];
    const float* Wq = (const float*)d_in[3];
    const float* bq = (const float*)d_in[4];
    const float* Wk = (const float*)d_in[5];
    const float* bk = (const float*)d_in[6];
    const float* Wv = (const float*)d_in[7];
    const float* bv = (const float*)d_in[8];
    const float* Wo = (const float*)d_in[9];
    const float* bo = (const float*)d_in[10];
    float* out = (float*)d_out;

    cudaFuncSetAttribute(gemm_qkv,
                         cudaFuncAttributeMaxDynamicSharedMemorySize, GEMM5_B);
    cudaFuncSetAttribute(gemm_out,
                         cudaFuncAttributeMaxDynamicSharedMemorySize, GEMM5_B);
    cudaFuncSetAttribute(flash_mma_kernel,
                         cudaFuncAttributeMaxDynamicSharedMemorySize, FLASH6_B);

    dim3 wgrid(512, 1, 4);
    split_w<<<wgrid, 256>>>(Wq, Wk, Wv, Wo);
    dim3 agrid(4096, 1, 3);
    split_act<<<agrid, 256>>>(q, k, v);

    dim3 qkv_grid(EE / 128, MM / 256, 3);   // (8, 16, 3) = 384 CTAs
    gemm_qkv<<<qkv_grid, 256, GEMM5_B>>>(bq, bk, bv);

    dim3 fa_grid(SS / 128, HH, BB);         // (16, 16, 2)
    flash_mma_kernel<<<fa_grid, 256, FLASH6_B>>>();

    dim3 ogrid(EE / 128, MM / 256);         // (8, 16)
    gemm_out<<<ogrid, 256, GEMM5_B>>>(bo, out);
}

// round 16
// speedup vs baseline: 1.5756x; 1.0291x over previous
#include <cuda_runtime.h>
#include <cuda_bf16.h>
#include <math.h>
#include <stdint.h>

#define BB 2
#define SS 2048
#define EE 1024
#define HH 16
#define DD 64
#define MM (BB * SS)
#define KP 512          // k-pairs per row (EE/2)

// ---------------- scratch (device globals; no allocations allowed) ----------
__device__ uint2 g_wsp[4][KP * EE];     // weights split: [kpair][n] {hi2,lo2}
__device__ uint2 g_asp[3][MM * KP];     // input activations split
__device__ uint2 g_qsp[MM * KP];        // projected Q, scaled+split
__device__ uint2 g_ksp[MM * KP];        // projected K, split
__device__ float g_vp [MM * EE];        // projected V, fp32
__device__ uint2 g_atsp[MM * KP];       // attention output, split

// ======================= helpers ============================================
__device__ __forceinline__ uint32_t smem_u32(const void* p) {
    uint32_t a;
    asm("{ .reg .u64 t; cvta.to.shared.u64 t, %1; cvt.u32.u64 %0, t; }"
        : "=r"(a) : "l"(p));
    return a;
}
__device__ __forceinline__ void cp16(uint32_t dst, const void* src) {
    asm volatile("cp.async.cg.shared.global [%0], [%1], 16;" :: "r"(dst), "l"(src));
}
#define CP_COMMIT() asm volatile("cp.async.commit_group;" ::: "memory")
#define CP_WAIT0()  asm volatile("cp.async.wait_group 0;" ::: "memory")
#define CP_WAIT1()  asm volatile("cp.async.wait_group 1;" ::: "memory")

__device__ __forceinline__ uint32_t packbf(float x0, float x1) {
    uint32_t r;
    asm("cvt.rn.bf16x2.f32 %0, %1, %2;" : "=r"(r) : "f"(x1), "f"(x0));
    return r;
}
__device__ __forceinline__ void bf_split2(float x0, float x1,
                                          uint32_t& h2, uint32_t& l2) {
    h2 = packbf(x0, x1);
    float h0 = __uint_as_float(h2 << 16);
    float h1 = __uint_as_float(h2 & 0xffff0000u);
    l2 = packbf(x0 - h0, x1 - h1);
}
__device__ __forceinline__ float ex2(float x) {
    float r;
    asm("ex2.approx.f32 %0, %1;" : "=f"(r) : "f"(x));
    return r;
}
__device__ __forceinline__ void mma_bf16(float* d, const uint32_t* a, const uint32_t* b) {
    asm volatile(
        "mma.sync.aligned.m16n8k16.row.col.f32.bf16.bf16.f32 "
        "{%0,%1,%2,%3}, {%4,%5,%6,%7}, {%8,%9}, {%0,%1,%2,%3};"
        : "+f"(d[0]), "+f"(d[1]), "+f"(d[2]), "+f"(d[3])
        : "r"(a[0]), "r"(a[1]), "r"(a[2]), "r"(a[3]), "r"(b[0]), "r"(b[1]));
}

// ======================= pre-split kernels (exact R12/R15) ==================
__global__ __launch_bounds__(256)
void split_w(const float* __restrict__ W0, const float* __restrict__ W1,
             const float* __restrict__ W2, const float* __restrict__ W3)
{
    const int z = blockIdx.z;
    const float* W = (z == 0) ? W0 : (z == 1) ? W1 : (z == 2) ? W2 : W3;
    uint2* out = g_wsp[z];
    const int idx = blockIdx.x * 256 + threadIdx.x;
    const int kp = idx >> 8;
    const int n = (idx & 255) * 4;
    float4 r0 = *(const float4*)&W[(size_t)(2 * kp) * EE + n];
    float4 r1 = *(const float4*)&W[(size_t)(2 * kp + 1) * EE + n];
    uint32_t hh, ll;
    bf_split2(r0.x, r1.x, hh, ll); out[(size_t)kp * EE + n + 0] = make_uint2(hh, ll);
    bf_split2(r0.y, r1.y, hh, ll); out[(size_t)kp * EE + n + 1] = make_uint2(hh, ll);
    bf_split2(r0.z, r1.z, hh, ll); out[(size_t)kp * EE + n + 2] = make_uint2(hh, ll);
    bf_split2(r0.w, r1.w, hh, ll); out[(size_t)kp * EE + n + 3] = make_uint2(hh, ll);
}

__global__ __launch_bounds__(256)
void split_act(const float* __restrict__ q, const float* __restrict__ k,
               const float* __restrict__ v)
{
    const int z = blockIdx.z;
    const float* src = (z == 0) ? q : (z == 1) ? k : v;
    uint2* out = g_asp[z];
    const int idx = blockIdx.x * 256 + threadIdx.x;
    const int row = idx >> 8;
    const int c = (idx & 255) * 4;
    float4 x = *(const float4*)&src[(size_t)row * EE + c];
    uint32_t hh, ll;
    bf_split2(x.x, x.y, hh, ll); out[(size_t)row * KP + c / 2]     = make_uint2(hh, ll);
    bf_split2(x.z, x.w, hh, ll); out[(size_t)row * KP + c / 2 + 1] = make_uint2(hh, ll);
}

// ======================= GEMM (exact R15: 256x128 CTA, warp 64x64) ==========
#define GA_STR 20
#define GB_STR 132
#define ST_A_U2 (256 * GA_STR)
#define ST_B_U2 (16 * GB_STR)
#define ST_U2 (ST_A_U2 + ST_B_U2)
#define GEMM5_B (3 * ST_U2 * 8)

#define QSCALE 0.18033688011112042591f  // 0.125 * log2(e)

__device__ __forceinline__ void gemm_body(const uint2* __restrict__ Asp,
                                          const uint2* __restrict__ Wsp,
                                          const float* __restrict__ bias,
                                          float* __restrict__ Cf,
                                          uint2* __restrict__ Cp,
                                          int mode)
{
    extern __shared__ uint2 su[];
    const uint32_t sb0 = smem_u32(su);

    const int tid = threadIdx.x;
    const int lane = tid & 31;
    const int wid = tid >> 5;
    const int warpM = wid >> 1;
    const int warpN = wid & 1;
    const int bm = blockIdx.y * 256;
    const int bn = blockIdx.x * 128;
    const int lg = lane >> 2;
    const int lt = lane & 3;

    float acc[4][8][4];
#pragma unroll
    for (int mi = 0; mi < 4; mi++)
#pragma unroll
        for (int ni = 0; ni < 8; ni++)
#pragma unroll
            for (int r = 0; r < 4; r++) acc[mi][ni][r] = 0.0f;

    auto load = [&](int it) {
        const int st = it % 3;
        const uint32_t sa = sb0 + (uint32_t)(st * ST_U2) * 8;
        const uint32_t sbp = sa + ST_A_U2 * 8;
#pragma unroll
        for (int i = 0; i < 8; i++) {
            int cid = tid + i * 256;
            int row = cid >> 3, c2 = (cid & 7) * 2;
            cp16(sa + (uint32_t)(row * GA_STR + c2) * 8,
                 Asp + (size_t)(bm + row) * KP + it * 16 + c2);
        }
#pragma unroll
        for (int i = 0; i < 4; i++) {
            int cid = tid + i * 256;
            int kp = cid >> 6, c = (cid & 63) * 2;
            cp16(sbp + (uint32_t)(kp * GB_STR + c) * 8,
                 Wsp + (size_t)(it * 16 + kp) * EE + bn + c);
        }
    };

    load(0); CP_COMMIT();
    load(1); CP_COMMIT();

    for (int it = 0; it < 32; it++) {
        if (it == 31) { CP_WAIT0(); } else { CP_WAIT1(); }
        __syncthreads();
        if (it + 2 < 32) { load(it + 2); CP_COMMIT(); }

        const uint2* Ah = su + (it % 3) * ST_U2;
        const uint2* Bh = Ah + ST_A_U2;

#pragma unroll
        for (int ks = 0; ks < 2; ks++) {
            uint32_t ah[4][4], al[4][4];
#pragma unroll
            for (int mi = 0; mi < 4; mi++) {
                int r = warpM * 64 + mi * 16 + lg;
                uint2 a0 = Ah[r * GA_STR + ks * 8 + lt];
                uint2 a1 = Ah[(r + 8) * GA_STR + ks * 8 + lt];
                uint2 a2 = Ah[r * GA_STR + ks * 8 + lt + 4];
                uint2 a3 = Ah[(r + 8) * GA_STR + ks * 8 + lt + 4];
                ah[mi][0] = a0.x; ah[mi][1] = a1.x; ah[mi][2] = a2.x; ah[mi][3] = a3.x;
                al[mi][0] = a0.y; al[mi][1] = a1.y; al[mi][2] = a2.y; al[mi][3] = a3.y;
            }
#pragma unroll
            for (int ni = 0; ni < 8; ni++) {
                int col = warpN * 64 + ni * 8 + lg;
                uint2 b0 = Bh[(ks * 8 + lt) * GB_STR + col];
                uint2 b1 = Bh[(ks * 8 + lt + 4) * GB_STR + col];
                uint32_t bh[2] = {b0.x, b1.x};
                uint32_t bl[2] = {b0.y, b1.y};
#pragma unroll
                for (int mi = 0; mi < 4; mi++) {
                    mma_bf16(acc[mi][ni], ah[mi], bh);
                    mma_bf16(acc[mi][ni], al[mi], bh);
                    mma_bf16(acc[mi][ni], ah[mi], bl);
                }
            }
        }
    }

    if (mode <= 1) {
        const float s = (mode == 0) ? QSCALE : 1.0f;
#pragma unroll
        for (int mi = 0; mi < 4; mi++) {
            const int row0 = bm + warpM * 64 + mi * 16 + lg;
#pragma unroll
            for (int ni = 0; ni < 8; ni++) {
                const int col = bn + warpN * 64 + ni * 8 + lt * 2;
                const float b0 = bias[col], b1 = bias[col + 1];
                uint32_t hh, ll;
                bf_split2((acc[mi][ni][0] + b0) * s, (acc[mi][ni][1] + b1) * s, hh, ll);
                Cp[(size_t)row0 * KP + col / 2] = make_uint2(hh, ll);
                bf_split2((acc[mi][ni][2] + b0) * s, (acc[mi][ni][3] + b1) * s, hh, ll);
                Cp[(size_t)(row0 + 8) * KP + col / 2] = make_uint2(hh, ll);
            }
        }
    } else {
#pragma unroll
        for (int mi = 0; mi < 4; mi++) {
            const int row0 = bm + warpM * 64 + mi * 16 + lg;
#pragma unroll
            for (int ni = 0; ni < 8; ni++) {
                const int col = bn + warpN * 64 + ni * 8 + lt * 2;
                const float b0 = bias[col], b1 = bias[col + 1];
                float2 v0 = make_float2(acc[mi][ni][0] + b0, acc[mi][ni][1] + b1);
                float2 v1 = make_float2(acc[mi][ni][2] + b0, acc[mi][ni][3] + b1);
                *(float2*)&Cf[(size_t)row0 * EE + col] = v0;
                *(float2*)&Cf[(size_t)(row0 + 8) * EE + col] = v1;
            }
        }
    }
}

__global__ __launch_bounds__(256, 1)
void gemm_qkv(const float* __restrict__ bq, const float* __restrict__ bk,
              const float* __restrict__ bv)
{
    const int z = blockIdx.z;
    const float* bias = (z == 0) ? bq : (z == 1) ? bk : bv;
    if (z == 0)      gemm_body(g_asp[0], g_wsp[0], bias, nullptr, g_qsp, 0);
    else if (z == 1) gemm_body(g_asp[1], g_wsp[1], bias, nullptr, g_ksp, 1);
    else             gemm_body(g_asp[2], g_wsp[2], bias, g_vp, nullptr, 2);
}

__global__ __launch_bounds__(256, 1)
void gemm_out(const float* __restrict__ bo, float* __restrict__ out)
{
    gemm_body(g_atsp, g_wsp[3], bo, out, nullptr, 3);
}

// ====== Flash attention: R15 structure, P kept in REGISTERS (no smem) =======
// The QK C-fragment layout (rows lg/lg+8, cols 2lt,2lt+1 per 8-col block)
// matches the PV A-fragment layout exactly:
//   a0 = pack(sacc[2ks][0,1])   (row lg,   keys 16ks+2lt,+1)
//   a1 = pack(sacc[2ks][2,3])   (row lg+8)
//   a2 = pack(sacc[2ks+1][0,1]) (row lg,   keys 16ks+8+2lt,+1)
//   a3 = pack(sacc[2ks+1][2,3]) (row lg+8)
#define PK_STR 36
#define FV_STR 68
#define OFF_V_U2 (64 * PK_STR)              // 2304 (Kh first)
#define FLASH9_U2 (OFF_V_U2 + 32 * FV_STR)  // 4480
#define FLASH9_B (FLASH9_U2 * 8)            // 35840 bytes

__global__ __launch_bounds__(256, 1)
void flash_mma_kernel()
{
    extern __shared__ uint2 su[];
    uint2* Kh = su;
    uint2* Vh = su + OFF_V_U2;

    const int tid = threadIdx.x;
    const int lane = tid & 31;
    const int w = tid >> 5;
    const int lg = lane >> 2;
    const int lt = lane & 3;
    const int qt = (gridDim.x - 1) - blockIdx.x;
    const int hd = blockIdx.y;
    const int b = blockIdx.z;
    const int qbase = qt * 128;
    const int hp = hd * 32;

    // Q fragments: direct LDG of pre-split, pre-scaled pairs
    const int r0 = w * 16 + lg;
    uint32_t qh[4][4], ql[4][4];
    {
        const size_t base0 = (size_t)(b * SS + qbase + r0) * KP + hp;
        const size_t base1 = base0 + 8 * KP;
#pragma unroll
        for (int ks = 0; ks < 4; ks++) {
            uint2 a0 = g_qsp[base0 + ks * 8 + lt];
            uint2 a1 = g_qsp[base1 + ks * 8 + lt];
            uint2 a2 = g_qsp[base0 + ks * 8 + lt + 4];
            uint2 a3 = g_qsp[base1 + ks * 8 + lt + 4];
            qh[ks][0] = a0.x; qh[ks][1] = a1.x; qh[ks][2] = a2.x; qh[ks][3] = a3.x;
            ql[ks][0] = a0.y; ql[ks][1] = a1.y; ql[ks][2] = a2.y; ql[ks][3] = a3.y;
        }
    }

    float oacc[8][4];
#pragma unroll
    for (int ni = 0; ni < 8; ni++)
#pragma unroll
        for (int r = 0; r < 4; r++) oacc[ni][r] = 0.0f;
    float m0 = -1e30f, m1 = -1e30f, l0 = 0.0f, l1 = 0.0f;

    const int nkt = (qbase + 128) / 64;

    for (int kt = 0; kt < nkt; kt++) {
        const int kbase = kt * 64;
        __syncthreads();
        // K tile: cp.async of pre-split pairs (zero CVT)
#pragma unroll
        for (int i = 0; i < 4; i++) {
            int cid = tid + i * 256;
            int row = cid >> 4, c2 = (cid & 15) * 2;
            cp16(smem_u32(Kh + row * PK_STR + c2),
                 g_ksp + (size_t)(b * SS + kbase + row) * KP + hp + c2);
        }
        CP_COMMIT();
        // V tile: fp32 -> split (pairs along key)
#pragma unroll
        for (int i = 0; i < 2; i++) {
            int s = tid + i * 256;
            int kp = s >> 4, c4 = (s & 15) * 4;
            const size_t g0 = ((size_t)(b * SS + kbase + 2 * kp)) * EE + hd * DD + c4;
            float4 va = *(const float4*)&g_vp[g0];
            float4 vb = *(const float4*)&g_vp[g0 + EE];
            uint32_t hh, ll;
            uint4 w0, w1;
            bf_split2(va.x, vb.x, hh, ll); w0.x = hh; w0.y = ll;
            bf_split2(va.y, vb.y, hh, ll); w0.z = hh; w0.w = ll;
            bf_split2(va.z, vb.z, hh, ll); w1.x = hh; w1.y = ll;
            bf_split2(va.w, vb.w, hh, ll); w1.z = hh; w1.w = ll;
            *(uint4*)&Vh[kp * FV_STR + c4] = w0;
            *(uint4*)&Vh[kp * FV_STR + c4 + 2] = w1;
        }
        CP_WAIT0();
        __syncthreads();

        // ---- S = Q @ K^T
        float sacc[8][4];
#pragma unroll
        for (int ni = 0; ni < 8; ni++)
#pragma unroll
            for (int r = 0; r < 4; r++) sacc[ni][r] = 0.0f;

#pragma unroll
        for (int ks = 0; ks < 4; ks++) {
#pragma unroll
            for (int ni = 0; ni < 8; ni++) {
                const int krow = ni * 8 + lg;
                uint2 k0 = Kh[krow * PK_STR + ks * 8 + lt];
                uint2 k1 = Kh[krow * PK_STR + ks * 8 + lt + 4];
                uint32_t bh[2] = {k0.x, k1.x};
                uint32_t bl[2] = {k0.y, k1.y};
                mma_bf16(sacc[ni], qh[ks], bh);
                mma_bf16(sacc[ni], ql[ks], bh);
                mma_bf16(sacc[ni], qh[ks], bl);
            }
        }

        if (kt >= 2 * qt) {
            const int grow0 = qbase + r0;
#pragma unroll
            for (int ni = 0; ni < 8; ni++) {
                const int c0 = kbase + ni * 8 + lt * 2;
                if (c0 > grow0)         sacc[ni][0] = -1e30f;
                if (c0 + 1 > grow0)     sacc[ni][1] = -1e30f;
                if (c0 > grow0 + 8)     sacc[ni][2] = -1e30f;
                if (c0 + 1 > grow0 + 8) sacc[ni][3] = -1e30f;
            }
        }

        // ---- online softmax (base-2)
        float rmax0 = -1e30f, rmax1 = -1e30f;
#pragma unroll
        for (int ni = 0; ni < 8; ni++) {
            rmax0 = fmaxf(rmax0, fmaxf(sacc[ni][0], sacc[ni][1]));
            rmax1 = fmaxf(rmax1, fmaxf(sacc[ni][2], sacc[ni][3]));
        }
        rmax0 = fmaxf(rmax0, __shfl_xor_sync(0xffffffffu, rmax0, 1));
        rmax0 = fmaxf(rmax0, __shfl_xor_sync(0xffffffffu, rmax0, 2));
        rmax1 = fmaxf(rmax1, __shfl_xor_sync(0xffffffffu, rmax1, 1));
        rmax1 = fmaxf(rmax1, __shfl_xor_sync(0xffffffffu, rmax1, 2));

        const float newm0 = fmaxf(m0, rmax0);
        const float newm1 = fmaxf(m1, rmax1);
        const float alpha0 = ex2(m0 - newm0);
        const float alpha1 = ex2(m1 - newm1);
        m0 = newm0; m1 = newm1;

        float rsum0 = 0.0f, rsum1 = 0.0f;
#pragma unroll
        for (int ni = 0; ni < 8; ni++) {
            sacc[ni][0] = ex2(sacc[ni][0] - m0);
            sacc[ni][1] = ex2(sacc[ni][1] - m0);
            sacc[ni][2] = ex2(sacc[ni][2] - m1);
            sacc[ni][3] = ex2(sacc[ni][3] - m1);
            rsum0 += sacc[ni][0] + sacc[ni][1];
            rsum1 += sacc[ni][2] + sacc[ni][3];
        }
        rsum0 += __shfl_xor_sync(0xffffffffu, rsum0, 1);
        rsum0 += __shfl_xor_sync(0xffffffffu, rsum0, 2);
        rsum1 += __shfl_xor_sync(0xffffffffu, rsum1, 1);
        rsum1 += __shfl_xor_sync(0xffffffffu, rsum1, 2);
        l0 = l0 * alpha0 + rsum0;
        l1 = l1 * alpha1 + rsum1;

        // rescale O (P stays in registers)
#pragma unroll
        for (int ni = 0; ni < 8; ni++) {
            oacc[ni][0] *= alpha0;
            oacc[ni][1] *= alpha0;
            oacc[ni][2] *= alpha1;
            oacc[ni][3] *= alpha1;
        }

        // ---- O += P @ V : P split+packed directly from sacc registers
#pragma unroll
        for (int ks = 0; ks < 4; ks++) {
            uint32_t ph[4], pl[4];
            bf_split2(sacc[2 * ks][0],     sacc[2 * ks][1],     ph[0], pl[0]);
            bf_split2(sacc[2 * ks][2],     sacc[2 * ks][3],     ph[1], pl[1]);
            bf_split2(sacc[2 * ks + 1][0], sacc[2 * ks + 1][1], ph[2], pl[2]);
            bf_split2(sacc[2 * ks + 1][2], sacc[2 * ks + 1][3], ph[3], pl[3]);
#pragma unroll
            for (int ni = 0; ni < 8; ni++) {
                const int col = ni * 8 + lg;
                uint2 v0 = Vh[(ks * 8 + lt) * FV_STR + col];
                uint2 v1 = Vh[(ks * 8 + lt + 4) * FV_STR + col];
                uint32_t bh[2] = {v0.x, v1.x};
                uint32_t bl[2] = {v0.y, v1.y};
                mma_bf16(oacc[ni], ph, bh);
                mma_bf16(oacc[ni], pl, bh);
                mma_bf16(oacc[ni], ph, bl);
            }
        }
    }

    // ---- epilogue: write attention output as split pairs for gemm_out
    const float inv0 = 1.0f / l0;
    const float inv1 = 1.0f / l1;
    const int grow = qbase + r0;
#pragma unroll
    for (int ni = 0; ni < 8; ni++) {
        uint32_t hh, ll;
        bf_split2(oacc[ni][0] * inv0, oacc[ni][1] * inv0, hh, ll);
        g_atsp[(size_t)(b * SS + grow) * KP + hp + ni * 4 + lt] = make_uint2(hh, ll);
        bf_split2(oacc[ni][2] * inv1, oacc[ni][3] * inv1, hh, ll);
        g_atsp[(size_t)(b * SS + grow + 8) * KP + hp + ni * 4 + lt] = make_uint2(hh, ll);
    }
}

// ---------------- launch ----------------------------------------------------
extern "C" void kernel_launch(void* const* d_in, const int* in_sizes, int n_in,
                              void* d_out, int out_size)
{
    const float* q  = (const float*)d_in[0];
    const float* k  = (const float*)d_in[1];
    const float* v  = (const float*)d_in[2];
    const float* Wq = (const float*)d_in[3];
    const float* bq = (const float*)d_in[4];
    const float* Wk = (const float*)d_in[5];
    const float* bk = (const float*)d_in[6];
    const float* Wv = (const float*)d_in[7];
    const float* bv = (const float*)d_in[8];
    const float* Wo = (const float*)d_in[9];
    const float* bo = (const float*)d_in[10];
    float* out = (float*)d_out;

    cudaFuncSetAttribute(gemm_qkv,
                         cudaFuncAttributeMaxDynamicSharedMemorySize, GEMM5_B);
    cudaFuncSetAttribute(gemm_out,
                         cudaFuncAttributeMaxDynamicSharedMemorySize, GEMM5_B);
    cudaFuncSetAttribute(flash_mma_kernel,
                         cudaFuncAttributeMaxDynamicSharedMemorySize, FLASH9_B);

    dim3 wgrid(512, 1, 4);
    split_w<<<wgrid, 256>>>(Wq, Wk, Wv, Wo);
    dim3 agrid(4096, 1, 3);
    split_act<<<agrid, 256>>>(q, k, v);

    dim3 qkv_grid(EE / 128, MM / 256, 3);   // (8, 16, 3)
    gemm_qkv<<<qkv_grid, 256, GEMM5_B>>>(bq, bk, bv);

    dim3 fa_grid(SS / 128, HH, BB);         // (16, 16, 2)
    flash_mma_kernel<<<fa_grid, 256, FLASH9_B>>>();

    dim3 ogrid(EE / 128, MM / 256);         // (8, 16)
    gemm_out<<<ogrid, 256, GEMM5_B>>>(bo, out);
}